// round 2
// baseline (speedup 1.0000x reference)
#include <cuda_runtime.h>
#include <math.h>

typedef unsigned long long ull;
#define DEV __device__ __forceinline__

// ---------- Blackwell packed fp32x2 helpers ----------
DEV ull splat2(float w) {
    ull r;
    asm("mov.b64 %0, {%1, %1};" : "=l"(r) : "f"(w));
    return r;
}
DEV void fma2(ull& d, ull a, ull b) {
    asm("fma.rn.f32x2 %0, %1, %2, %0;" : "+l"(d) : "l"(a), "l"(b));
}
DEV float2 unpack2(ull v) {
    float2 f;
    asm("mov.b64 {%0, %1}, %2;" : "=f"(f.x), "=f"(f.y) : "l"(v));
    return f;
}

DEV float sigf(float x) {
    x = fminf(fmaxf(x, -30.0f), 30.0f);
    return __fdividef(1.0f, 1.0f + __expf(-x));
}
DEV float tanhf_(float x) {
    x = fminf(fmaxf(x, -15.0f), 15.0f);
    return 1.0f - __fdividef(2.0f, 1.0f + __expf(2.0f * x));
}

// Problem constants: x [B=256][T=24][D=2][N=512]; H=128, 3H=384; sensor tile 64.
#define NT 64

// SMEM float offsets
#define OFF_WS0   0
#define OFF_WS1   12288
#define OFF_H0    24576
#define OFF_H1    32768
#define OFF_H2    40960
#define OFF_WX0   49152
#define OFF_BX0   49920
#define OFF_BH0   50304
#define OFF_BX1   50688
#define OFF_BH1   51072
#define SMEM_FLOATS 51456   /* 205824 bytes */

// Copy weight chunk tile: W[128][384] global -> ws[128][96]
// (cols g*128 + c*32 .. +32 for each gate g). 3072 float4 moves, 12/thread.
DEV void stage_tile(float* __restrict__ dst, const float* __restrict__ W,
                    int c, int tid) {
    const float* src = W + c * 32;
    #pragma unroll
    for (int i = 0; i < 12; i++) {
        int q = tid + 256 * i;
        int k = q / 24;
        int rem = q - 24 * k;
        int g = rem >> 3;
        int p = rem & 7;
        float4 v = *(const float4*)(src + k * 384 + g * 128 + p * 4);
        *(float4*)(dst + k * 96 + g * 32 + p * 4) = v;
    }
}

// acc[g*4 + {0,1,2,3}] = {row0·cols01, row0·cols23, row1·cols01, row1·cols23}
DEV void mv_acc(ull* acc, const float* __restrict__ Wc,
                const float* __restrict__ hc, int ty, int tx) {
    const float* wp = Wc + 2 * ty;
    const float* hp = hc + 4 * tx;
    #pragma unroll 4
    for (int k = 0; k < 128; k++) {
        ulonglong2 h2 = *(const ulonglong2*)hp;   // LDS.128, broadcast-friendly
        #pragma unroll
        for (int g = 0; g < 3; g++) {
            float2 w = *(const float2*)(wp + 32 * g);
            ull a0 = splat2(w.x), a1 = splat2(w.y);
            fma2(acc[g * 4 + 0], a0, h2.x);
            fma2(acc[g * 4 + 1], a0, h2.y);
            fma2(acc[g * 4 + 2], a1, h2.x);
            fma2(acc[g * 4 + 3], a1, h2.y);
        }
        wp += 96;
        hp += 64;
    }
}

DEV void unpack_gate(float o[2][4], const ull* a) {
    float2 u;
    u = unpack2(a[0]); o[0][0] = u.x; o[0][1] = u.y;
    u = unpack2(a[1]); o[0][2] = u.x; o[0][3] = u.y;
    u = unpack2(a[2]); o[1][0] = u.x; o[1][1] = u.y;
    u = unpack2(a[3]); o[1][2] = u.x; o[1][3] = u.y;
}

__global__ void __launch_bounds__(256, 1) gru2_kernel(
    const float* __restrict__ x,
    const float* __restrict__ Wx0, const float* __restrict__ Wh0,
    const float* __restrict__ bx0, const float* __restrict__ bh0,
    const float* __restrict__ Wx1, const float* __restrict__ Wh1,
    const float* __restrict__ bx1, const float* __restrict__ bh1,
    float* __restrict__ out)
{
    extern __shared__ float sm[];
    float* ws0  = sm + OFF_WS0;
    float* ws1  = sm + OFF_WS1;
    float* wx0s = sm + OFF_WX0;
    float* bx0s = sm + OFF_BX0;
    float* bh0s = sm + OFF_BH0;
    float* bx1s = sm + OFF_BX1;
    float* bh1s = sm + OFF_BH1;

    const int tid = threadIdx.x;
    const int tx = tid & 15;     // sensor col group (4 cols)
    const int ty = tid >> 4;     // gate row pair within 32-row chunk
    const int b = blockIdx.y;
    const int nbase = blockIdx.x * NT;

    // constants + zero initial state
    for (int i = tid; i < 384; i += 256) {
        bx0s[i] = bx0[i]; bh0s[i] = bh0[i];
        bx1s[i] = bx1[i]; bh1s[i] = bh1[i];
    }
    for (int i = tid; i < 768; i += 256) wx0s[i] = Wx0[i];
    for (int i = tid; i < 8192; i += 256) {
        sm[OFF_H0 + i] = 0.0f;
        sm[OFF_H1 + i] = 0.0f;
    }
    __syncthreads();

    float* pA = sm + OFF_H0;  // h0_old
    float* pB = sm + OFF_H1;  // h1_old
    float* pC = sm + OFF_H2;  // free -> receives h0_new

    #pragma unroll 1
    for (int t = 0; t < 24; t++) {
        // this thread's x values (4 sensor cols, D=2)
        float x0v[4], x1v[4];
        {
            const float* xp = x + ((size_t)b * 24 + t) * 1024 + nbase + 4 * tx;
            float4 v0 = *(const float4*)(xp);
            float4 v1 = *(const float4*)(xp + 512);
            x0v[0] = v0.x; x0v[1] = v0.y; x0v[2] = v0.z; x0v[3] = v0.w;
            x1v[0] = v1.x; x1v[1] = v1.y; x1v[2] = v1.z; x1v[3] = v1.w;
        }

        // ---------------- Layer 0 ----------------
        #pragma unroll 1
        for (int c = 0; c < 4; c++) {
            stage_tile(ws0, Wh0, c, tid);
            __syncthreads();

            ull acc[12];
            #pragma unroll
            for (int i = 0; i < 12; i++) acc[i] = 0ull;
            mv_acc(acc, ws0, pA, ty, tx);

            float aR[2][4], aZ[2][4], aN[2][4];
            unpack_gate(aR, acc + 0);
            unpack_gate(aZ, acc + 4);
            unpack_gate(aN, acc + 8);

            #pragma unroll
            for (int rr = 0; rr < 2; rr++) {
                int jj = c * 32 + 2 * ty + rr;
                float bR  = bx0s[jj] + bh0s[jj];
                float bZ  = bx0s[128 + jj] + bh0s[128 + jj];
                float bxn = bx0s[256 + jj];
                float bhn = bh0s[256 + jj];
                float wr0 = wx0s[jj],       wr1 = wx0s[384 + jj];
                float wz0 = wx0s[128 + jj], wz1 = wx0s[512 + jj];
                float wn0 = wx0s[256 + jj], wn1 = wx0s[640 + jj];
                float4 hv = *(const float4*)&pA[jj * 64 + 4 * tx];
                float ho[4] = { hv.x, hv.y, hv.z, hv.w };
                float res[4];
                #pragma unroll
                for (int cc = 0; cc < 4; cc++) {
                    float rg = sigf(aR[rr][cc] + wr0 * x0v[cc] + wr1 * x1v[cc] + bR);
                    float zg = sigf(aZ[rr][cc] + wz0 * x0v[cc] + wz1 * x1v[cc] + bZ);
                    float ng = tanhf_(wn0 * x0v[cc] + wn1 * x1v[cc] + bxn
                                      + rg * (aN[rr][cc] + bhn));
                    res[cc] = (1.0f - zg) * ng + zg * ho[cc];
                }
                *(float4*)&pC[jj * 64 + 4 * tx] =
                    make_float4(res[0], res[1], res[2], res[3]);
            }
            __syncthreads();
        }

        // ---------------- Layer 1 ----------------
        #pragma unroll 1
        for (int c = 0; c < 4; c++) {
            stage_tile(ws0, Wx1, c, tid);
            stage_tile(ws1, Wh1, c, tid);
            __syncthreads();

            ull accI[12], accH[12];
            #pragma unroll
            for (int i = 0; i < 12; i++) { accI[i] = 0ull; accH[i] = 0ull; }
            mv_acc(accI, ws0, pC, ty, tx);  // Wx1^T * h0_new
            mv_acc(accH, ws1, pB, ty, tx);  // Wh1^T * h1_old

            float aIr[2][4], aIz[2][4], aIn[2][4];
            float aHr[2][4], aHz[2][4], aHn[2][4];
            unpack_gate(aIr, accI + 0);
            unpack_gate(aIz, accI + 4);
            unpack_gate(aIn, accI + 8);
            unpack_gate(aHr, accH + 0);
            unpack_gate(aHz, accH + 4);
            unpack_gate(aHn, accH + 8);

            #pragma unroll
            for (int rr = 0; rr < 2; rr++) {
                int jj = c * 32 + 2 * ty + rr;
                float bR  = bx1s[jj] + bh1s[jj];
                float bZ  = bx1s[128 + jj] + bh1s[128 + jj];
                float bxn = bx1s[256 + jj];
                float bhn = bh1s[256 + jj];
                float4 hv = *(const float4*)&pB[jj * 64 + 4 * tx];
                float ho[4] = { hv.x, hv.y, hv.z, hv.w };
                float res[4];
                #pragma unroll
                for (int cc = 0; cc < 4; cc++) {
                    float rg = sigf(aIr[rr][cc] + aHr[rr][cc] + bR);
                    float zg = sigf(aIz[rr][cc] + aHz[rr][cc] + bZ);
                    float ng = tanhf_(aIn[rr][cc] + bxn + rg * (aHn[rr][cc] + bhn));
                    res[cc] = (1.0f - zg) * ng + zg * ho[cc];
                }
                *(float4*)&pA[jj * 64 + 4 * tx] =
                    make_float4(res[0], res[1], res[2], res[3]);
            }
            __syncthreads();
        }

        // rotate: h0_old <- pC (h0_new), h1_old <- pA (h1_new), free <- pB
        float* t0 = pA;
        pA = pC;
        pC = pB;
        pB = t0;
    }

    // write final states: out[2][256][128][512]; pA = h0, pB = h1
    #pragma unroll
    for (int i = tid; i < 2048; i += 256) {
        int jj = i >> 4;
        int cg = i & 15;
        float4 v0 = *(const float4*)&pA[jj * 64 + cg * 4];
        float4 v1 = *(const float4*)&pB[jj * 64 + cg * 4];
        size_t o0 = (size_t)b * 65536 + (size_t)jj * 512 + nbase + cg * 4;
        *(float4*)&out[o0] = v0;
        *(float4*)&out[16777216 + o0] = v1;
    }
}

extern "C" void kernel_launch(void* const* d_in, const int* in_sizes, int n_in,
                              void* d_out, int out_size) {
    const float* x   = (const float*)d_in[0];
    const float* Wx0 = (const float*)d_in[1];
    const float* Wh0 = (const float*)d_in[2];
    const float* bx0 = (const float*)d_in[3];
    const float* bh0 = (const float*)d_in[4];
    const float* Wx1 = (const float*)d_in[5];
    const float* Wh1 = (const float*)d_in[6];
    const float* bx1 = (const float*)d_in[7];
    const float* bh1 = (const float*)d_in[8];
    float* out = (float*)d_out;

    cudaFuncSetAttribute(gru2_kernel,
                         cudaFuncAttributeMaxDynamicSharedMemorySize,
                         SMEM_FLOATS * sizeof(float));
    dim3 grid(512 / NT, 256);
    gru2_kernel<<<grid, 256, SMEM_FLOATS * sizeof(float)>>>(
        x, Wx0, Wh0, bx0, bh0, Wx1, Wh1, bx1, bh1, out);
}